// round 12
// baseline (speedup 1.0000x reference)
#include <cuda_runtime.h>
#include <cstdint>
#include <cstddef>

// Problem constants
#define M_TOK  8192
#define D_IN   4096
#define D_OUT  4096
#define NE     32
#define ER     512
#define SCALING 2.0f

// Scratch (__device__ globals are the sanctioned workaround)
__device__ float g_xr [(size_t)M_TOK * D_IN];   // 128 MB: tf32-rounded x
__device__ float g_bwr[(size_t)D_OUT * D_IN];   //  64 MB: tf32-rounded base_w
__device__ float g_lar[(size_t)ER * D_IN];      //   8 MB: tf32-rounded lora_A
__device__ float g_lbr[(size_t)D_OUT * ER];     //   8 MB: tf32-rounded lora_B
__device__ float g_axw[(size_t)M_TOK * ER];     //  16 MB: (x@A^T)*w*SCALING (tf32-rounded)
__device__ float g_w  [(size_t)M_TOK * NE];     //   1 MB: gate weights * SCALING

// ---------------------------------------------------------------------------
// helpers
// ---------------------------------------------------------------------------
__device__ __forceinline__ uint32_t smem_u32(const void* p) {
    uint32_t a;
    asm("{ .reg .u64 t; cvta.to.shared.u64 t, %1; cvt.u32.u64 %0, t; }" : "=r"(a) : "l"(p));
    return a;
}
__device__ __forceinline__ float f2tf32(float x) {
    uint32_t r; asm("cvt.rna.tf32.f32 %0, %1;" : "=r"(r) : "f"(x));
    return __uint_as_float(r);
}
__device__ __forceinline__ void mma_tf32(float* c, const uint32_t* a, const uint32_t* b) {
    asm volatile(
        "mma.sync.aligned.m16n8k8.row.col.f32.tf32.tf32.f32 "
        "{%0,%1,%2,%3}, {%4,%5,%6,%7}, {%8,%9}, {%0,%1,%2,%3};\n"
        : "+f"(c[0]), "+f"(c[1]), "+f"(c[2]), "+f"(c[3])
        : "r"(a[0]), "r"(a[1]), "r"(a[2]), "r"(a[3]),
          "r"(b[0]), "r"(b[1]));
}
#define CP_ASYNC16(dst, src) \
    asm volatile("cp.async.cg.shared.global [%0], [%1], 16;" :: "r"(dst), "l"(src) : "memory")
#define CP_COMMIT() asm volatile("cp.async.commit_group;" ::: "memory")
#define CP_WAIT(n)  asm volatile("cp.async.wait_group %0;" :: "n"(n) : "memory")

// ---------------------------------------------------------------------------
// Kernel 0: elementwise tf32 rounding (RNA), vectorized
// ---------------------------------------------------------------------------
__global__ __launch_bounds__(256)
void round_kernel(const float* __restrict__ in, float* __restrict__ out, int n4) {
    const float4* i4 = (const float4*)in;
    float4* o4 = (float4*)out;
    for (int i = blockIdx.x * blockDim.x + threadIdx.x; i < n4; i += gridDim.x * blockDim.x) {
        float4 q = i4[i];
        q.x = f2tf32(q.x); q.y = f2tf32(q.y);
        q.z = f2tf32(q.z); q.w = f2tf32(q.w);
        o4[i] = q;
    }
}

// ---------------------------------------------------------------------------
// Kernel 1: gating, 32 tokens/block (measured R3: 162us). Reads original x.
// ---------------------------------------------------------------------------
#define GT_TOK 32
#define GT_DC  128
#define GT_LDX 132

__global__ __launch_bounds__(256)
void gate_kernel(const float* __restrict__ x,
                 const float* __restrict__ gw,
                 float* __restrict__ wout)
{
    __shared__ float xs[GT_TOK][GT_LDX];
    __shared__ float gs[NE][GT_DC];
    __shared__ float logits[GT_TOK][NE + 1];
    __shared__ float sval[GT_TOK][2];
    __shared__ int   sidx[GT_TOK][2];

    const int t   = threadIdx.x;
    const int tok = t & 31;
    const int eg  = t >> 5;
    const size_t tok0 = (size_t)blockIdx.x * GT_TOK;

    float acc[4] = {0.f, 0.f, 0.f, 0.f};

    for (int d0 = 0; d0 < D_IN; d0 += GT_DC) {
        __syncthreads();
        #pragma unroll
        for (int i = 0; i < 4; i++) {
            const int idx4 = t + 256 * i;
            const int row  = idx4 >> 5;
            const int col4 = (idx4 & 31) * 4;
            float4 v = *(const float4*)&x[(tok0 + row) * D_IN + d0 + col4];
            *(float4*)&xs[row][col4] = v;
            float4 g = *(const float4*)&gw[(size_t)row * D_IN + d0 + col4];
            *(float4*)&gs[row][col4] = g;
        }
        __syncthreads();
        #pragma unroll 8
        for (int dq = 0; dq < GT_DC; dq += 4) {
            float4 xv = *(const float4*)&xs[tok][dq];
            #pragma unroll
            for (int j = 0; j < 4; j++) {
                float4 gv = *(const float4*)&gs[eg * 4 + j][dq];
                acc[j] += xv.x * gv.x + xv.y * gv.y + xv.z * gv.z + xv.w * gv.w;
            }
        }
    }
    __syncthreads();
    #pragma unroll
    for (int j = 0; j < 4; j++) logits[tok][eg * 4 + j] = acc[j];
    __syncthreads();

    if (t < GT_TOK) {
        int   i1 = 0; float v1 = logits[t][0];
        #pragma unroll
        for (int k = 1; k < NE; k++) { float v = logits[t][k]; if (v > v1) { v1 = v; i1 = k; } }
        int   i2 = -1; float v2 = -3.0e38f;
        #pragma unroll
        for (int k = 0; k < NE; k++) { float v = logits[t][k]; if (k != i1 && v > v2) { v2 = v; i2 = k; } }
        float p1 = 1.0f / (1.0f + expf(v2 - v1));
        sidx[t][0] = i1; sidx[t][1] = i2;
        sval[t][0] = p1 * SCALING; sval[t][1] = (1.0f - p1) * SCALING;
    }
    __syncthreads();

    #pragma unroll
    for (int i = 0; i < 4; i++) {
        const int idx = t + 256 * i;
        const int tk  = idx >> 5;
        const int e   = idx & 31;
        float v = 0.f;
        if (e == sidx[tk][0]) v = sval[tk][0];
        else if (e == sidx[tk][1]) v = sval[tk][1];
        wout[(tok0 + tk) * NE + e] = v;
    }
}

// ---------------------------------------------------------------------------
// Kernel 2/3: multistage cp.async TF32 mma.sync GEMM, dual K-segment.
//   C[m,n] = sum A1[m,:]W1[n,:] (+ sum A2[m,:]W2[n,:])
// Inputs PRE-ROUNDED to tf32 (no converts in mainloop).
// CTA tile 128(M) x 256(N), BK=32, 4 stages, 256 threads.
// Warp grid 2x4, warp tile 64x64 -> 16 FLOP per smem byte (vs 10.9 at 64x32):
// crossbar ceiling ~546 TF/s. Occupancy 1 (128 acc regs), compensated by
// 4-stage cp.async (prefetch distance 3).
// Smem row stride 36 floats: cp.async 16B-aligned AND conflict-free fragment
// LDS (bank = 4g+tg, all 32 distinct per warp).
// One __syncthreads per K-tile: any thread past barrier(kt) implies all
// threads finished compute(kt-1); issue(kt+3) targets buffer (kt-1)%4 — safe.
// EPI==1: scale output by wg[row*NE + col/16] and re-round to tf32 (feeds gemm3).
// ---------------------------------------------------------------------------
#define BK     32
#define LDA    36                   // padded row stride (floats)
#define ASTR   (128 * LDA)          // A tile floats per stage
#define BSTR   (256 * LDA)          // B tile floats per stage
#define STAGES 4

template<int EPI>
__global__ __launch_bounds__(256, 1)
void mma_gemm(const float* __restrict__ A1, const float* __restrict__ W1, int k1, int nt1,
              const float* __restrict__ A2, const float* __restrict__ W2, int k2, int nt2,
              float* __restrict__ C, int Nout,
              const float* __restrict__ wg)
{
    extern __shared__ float sm[];   // [4 A-stages][4 B-stages]

    const int t    = threadIdx.x;
    const int warp = t >> 5;
    const int lane = t & 31;
    const int m0   = blockIdx.y * 128;
    const int n0   = blockIdx.x * 256;
    const int wm   = (warp & 1) * 64;      // 2 warp rows
    const int wn   = (warp >> 1) * 64;     // 4 warp cols, 64 wide each
    const int g    = lane >> 2;
    const int tg   = lane & 3;
    const int nt   = nt1 + nt2;

    float acc[4][8][4];
    #pragma unroll
    for (int i = 0; i < 4; i++)
        #pragma unroll
        for (int j = 0; j < 8; j++)
            #pragma unroll
            for (int k = 0; k < 4; k++)
                acc[i][j][k] = 0.f;

    const uint32_t smU = smem_u32(sm);

    auto issue = [&](int kt, int s) {
        const float* As; const float* Ws; int ks, koff;
        if (kt < nt1) { As = A1; Ws = W1; ks = k1; koff = kt * BK; }
        else          { As = A2; Ws = W2; ks = k2; koff = (kt - nt1) * BK; }
        const uint32_t aU = smU + (uint32_t)(s * ASTR) * 4u;
        const uint32_t bU = smU + (uint32_t)(STAGES * ASTR + s * BSTR) * 4u;
        #pragma unroll
        for (int i = 0; i < 4; i++) {          // A: 128 rows x 8 chunks
            const int ch = i * 256 + t;
            const int row = ch >> 3, kc = (ch & 7) * 4;
            CP_ASYNC16(aU + (uint32_t)(row * LDA + kc) * 4u,
                       As + (size_t)(m0 + row) * ks + koff + kc);
        }
        #pragma unroll
        for (int i = 0; i < 8; i++) {          // B: 256 rows x 8 chunks
            const int ch = i * 256 + t;
            const int row = ch >> 3, kc = (ch & 7) * 4;
            CP_ASYNC16(bU + (uint32_t)(row * LDA + kc) * 4u,
                       Ws + (size_t)(n0 + row) * ks + koff + kc);
        }
    };

    // prologue: stages 0..2 in flight
    issue(0, 0); CP_COMMIT();
    issue(1, 1); CP_COMMIT();
    issue(2, 2); CP_COMMIT();

    for (int kt = 0; kt < nt; kt++) {
        const int s = kt % STAGES;
        CP_WAIT(2);                 // tile kt's group complete
        __syncthreads();

        const float* as = sm + s * ASTR;
        const float* bs = sm + STAGES * ASTR + s * BSTR;

        #pragma unroll
        for (int ks = 0; ks < BK; ks += 8) {
            uint32_t af[4][4], bf[8][2];
            #pragma unroll
            for (int i = 0; i < 4; i++) {
                const int mb = wm + i * 16;
                af[i][0] = __float_as_uint(as[(mb + g    ) * LDA + ks + tg    ]);
                af[i][1] = __float_as_uint(as[(mb + g + 8) * LDA + ks + tg    ]);
                af[i][2] = __float_as_uint(as[(mb + g    ) * LDA + ks + tg + 4]);
                af[i][3] = __float_as_uint(as[(mb + g + 8) * LDA + ks + tg + 4]);
            }
            #pragma unroll
            for (int j = 0; j < 8; j++) {
                const int nb = wn + j * 8 + g;
                bf[j][0] = __float_as_uint(bs[nb * LDA + ks + tg    ]);
                bf[j][1] = __float_as_uint(bs[nb * LDA + ks + tg + 4]);
            }
            #pragma unroll
            for (int i = 0; i < 4; i++)
                #pragma unroll
                for (int j = 0; j < 8; j++)
                    mma_tf32(acc[i][j], af[i], bf[j]);
        }

        if (kt + 3 < nt) issue(kt + 3, (kt + 3) % STAGES);
        CP_COMMIT();                // one commit per iteration keeps group count aligned
    }

    // epilogue
    #pragma unroll
    for (int i = 0; i < 4; i++) {
        const int mrow = m0 + wm + i * 16 + g;
        #pragma unroll
        for (int j = 0; j < 8; j++) {
            const int ncol = n0 + wn + j * 8 + tg * 2;
            float s0 = 1.f, s1 = 1.f;
            if (EPI) {
                s0 = wg[(size_t)mrow       * NE + (ncol >> 4)];
                s1 = wg[(size_t)(mrow + 8) * NE + (ncol >> 4)];
            }
            float2 v0, v1;
            if (EPI) {   // feeds gemm3 as a tf32 operand: round now
                v0.x = f2tf32(acc[i][j][0] * s0); v0.y = f2tf32(acc[i][j][1] * s0);
                v1.x = f2tf32(acc[i][j][2] * s1); v1.y = f2tf32(acc[i][j][3] * s1);
            } else {
                v0.x = acc[i][j][0]; v0.y = acc[i][j][1];
                v1.x = acc[i][j][2]; v1.y = acc[i][j][3];
            }
            *(float2*)&C[(size_t)mrow       * Nout + ncol] = v0;
            *(float2*)&C[(size_t)(mrow + 8) * Nout + ncol] = v1;
        }
    }
}

// ---------------------------------------------------------------------------
// launch
// ---------------------------------------------------------------------------
extern "C" void kernel_launch(void* const* d_in, const int* in_sizes, int n_in,
                              void* d_out, int out_size) {
    const float* x      = (const float*)d_in[0];
    const float* base_w = (const float*)d_in[1];
    const float* gate_w = (const float*)d_in[2];
    const float* lora_A = (const float*)d_in[3];
    const float* lora_B = (const float*)d_in[4];
    float* out = (float*)d_out;

    float *xr, *bwr, *lar, *lbr, *axw, *wbuf;
    cudaGetSymbolAddress((void**)&xr,   g_xr);
    cudaGetSymbolAddress((void**)&bwr,  g_bwr);
    cudaGetSymbolAddress((void**)&lar,  g_lar);
    cudaGetSymbolAddress((void**)&lbr,  g_lbr);
    cudaGetSymbolAddress((void**)&axw,  g_axw);
    cudaGetSymbolAddress((void**)&wbuf, g_w);

    const int smem = STAGES * (ASTR + BSTR) * 4;   // 221184 B
    cudaFuncSetAttribute(mma_gemm<0>, cudaFuncAttributeMaxDynamicSharedMemorySize, smem);
    cudaFuncSetAttribute(mma_gemm<1>, cudaFuncAttributeMaxDynamicSharedMemorySize, smem);

    // 0) pre-round GEMM operands to tf32 (RNA)
    round_kernel<<<2048, 256>>>(x,      xr,  (int)((size_t)M_TOK * D_IN / 4));
    round_kernel<<<1024, 256>>>(base_w, bwr, (int)((size_t)D_OUT * D_IN / 4));
    round_kernel<<<512,  256>>>(lora_A, lar, (int)((size_t)ER * D_IN / 4));
    round_kernel<<<512,  256>>>(lora_B, lbr, (int)((size_t)D_OUT * ER / 4));

    // 1) gate weights (original x)
    gate_kernel<<<M_TOK / GT_TOK, 256>>>(x, gate_w, wbuf);

    // 2) axw = (x @ lora_A^T) * w * SCALING   [8192, 512] (tf32-rounded)
    {
        dim3 grid(ER / 256, M_TOK / 128);     // (2, 64)
        mma_gemm<1><<<grid, 256, smem>>>(xr, lar, D_IN, D_IN / BK,
                                         nullptr, nullptr, 0, 0,
                                         axw, ER, wbuf);
    }

    // 3) out = x @ base_w^T + axw @ lora_B^T  [8192, 4096]
    {
        dim3 grid(D_OUT / 256, M_TOK / 128);  // (16, 64)
        mma_gemm<0><<<grid, 256, smem>>>(xr, bwr, D_IN, D_IN / BK,
                                         axw, lbr, ER, ER / BK,
                                         out, D_OUT, nullptr);
    }
}

// round 17
// speedup vs baseline: 1.6729x; 1.6729x over previous
#include <cuda_runtime.h>
#include <cuda_fp16.h>
#include <cstdint>
#include <cstddef>

// Problem constants
#define M_TOK  8192
#define D_IN   4096
#define D_OUT  4096
#define NE     32
#define ER     512
#define SCALING 2.0f

// Scratch (__device__ globals are the sanctioned workaround)
__device__ __half g_xh [(size_t)M_TOK * D_IN];   // 64 MB: fp16 x
__device__ __half g_bwh[(size_t)D_OUT * D_IN];   // 32 MB: fp16 base_w
__device__ __half g_lah[(size_t)ER * D_IN];      //  4 MB: fp16 lora_A
__device__ __half g_lbh[(size_t)D_OUT * ER];     //  4 MB: fp16 lora_B
__device__ __half g_axw[(size_t)M_TOK * ER];     //  8 MB: fp16 (x@A^T)*w*SCALING
__device__ float  g_w  [(size_t)M_TOK * NE];     //  1 MB: gate weights * SCALING

// ---------------------------------------------------------------------------
// helpers
// ---------------------------------------------------------------------------
__device__ __forceinline__ uint32_t smem_u32(const void* p) {
    uint32_t a;
    asm("{ .reg .u64 t; cvta.to.shared.u64 t, %1; cvt.u32.u64 %0, t; }" : "=r"(a) : "l"(p));
    return a;
}
// fp16 MMA, fp32 accumulate: D = A(16x16) * B(16x8) + D
__device__ __forceinline__ void mma_f16(float* c, const uint32_t* a, const uint32_t* b) {
    asm volatile(
        "mma.sync.aligned.m16n8k16.row.col.f32.f16.f16.f32 "
        "{%0,%1,%2,%3}, {%4,%5,%6,%7}, {%8,%9}, {%0,%1,%2,%3};\n"
        : "+f"(c[0]), "+f"(c[1]), "+f"(c[2]), "+f"(c[3])
        : "r"(a[0]), "r"(a[1]), "r"(a[2]), "r"(a[3]),
          "r"(b[0]), "r"(b[1]));
}
#define CP_ASYNC16(dst, src) \
    asm volatile("cp.async.cg.shared.global [%0], [%1], 16;" :: "r"(dst), "l"(src) : "memory")
#define CP_COMMIT() asm volatile("cp.async.commit_group;" ::: "memory")
#define CP_WAIT(n)  asm volatile("cp.async.wait_group %0;" :: "n"(n) : "memory")

// ---------------------------------------------------------------------------
// Kernel 0: fp32 -> fp16 conversion (RN), vectorized
// ---------------------------------------------------------------------------
__global__ __launch_bounds__(256)
void cvt_kernel(const float* __restrict__ in, __half* __restrict__ out, int n4) {
    const float4* i4 = (const float4*)in;
    uint2* o4 = (uint2*)out;     // 4 halves
    for (int i = blockIdx.x * blockDim.x + threadIdx.x; i < n4; i += gridDim.x * blockDim.x) {
        float4 q = i4[i];
        __half2 lo = __floats2half2_rn(q.x, q.y);
        __half2 hi = __floats2half2_rn(q.z, q.w);
        uint2 o;
        o.x = *(uint32_t*)&lo;
        o.y = *(uint32_t*)&hi;
        o4[i] = o;
    }
}

// ---------------------------------------------------------------------------
// Kernel 1: gating, 32 tokens/block (measured R3: 162us). Reads original x.
// ---------------------------------------------------------------------------
#define GT_TOK 32
#define GT_DC  128
#define GT_LDX 132

__global__ __launch_bounds__(256)
void gate_kernel(const float* __restrict__ x,
                 const float* __restrict__ gw,
                 float* __restrict__ wout)
{
    __shared__ float xs[GT_TOK][GT_LDX];
    __shared__ float gs[NE][GT_DC];
    __shared__ float logits[GT_TOK][NE + 1];
    __shared__ float sval[GT_TOK][2];
    __shared__ int   sidx[GT_TOK][2];

    const int t   = threadIdx.x;
    const int tok = t & 31;
    const int eg  = t >> 5;
    const size_t tok0 = (size_t)blockIdx.x * GT_TOK;

    float acc[4] = {0.f, 0.f, 0.f, 0.f};

    for (int d0 = 0; d0 < D_IN; d0 += GT_DC) {
        __syncthreads();
        #pragma unroll
        for (int i = 0; i < 4; i++) {
            const int idx4 = t + 256 * i;
            const int row  = idx4 >> 5;
            const int col4 = (idx4 & 31) * 4;
            float4 v = *(const float4*)&x[(tok0 + row) * D_IN + d0 + col4];
            *(float4*)&xs[row][col4] = v;
            float4 g = *(const float4*)&gw[(size_t)row * D_IN + d0 + col4];
            *(float4*)&gs[row][col4] = g;
        }
        __syncthreads();
        #pragma unroll 8
        for (int dq = 0; dq < GT_DC; dq += 4) {
            float4 xv = *(const float4*)&xs[tok][dq];
            #pragma unroll
            for (int j = 0; j < 4; j++) {
                float4 gv = *(const float4*)&gs[eg * 4 + j][dq];
                acc[j] += xv.x * gv.x + xv.y * gv.y + xv.z * gv.z + xv.w * gv.w;
            }
        }
    }
    __syncthreads();
    #pragma unroll
    for (int j = 0; j < 4; j++) logits[tok][eg * 4 + j] = acc[j];
    __syncthreads();

    if (t < GT_TOK) {
        int   i1 = 0; float v1 = logits[t][0];
        #pragma unroll
        for (int k = 1; k < NE; k++) { float v = logits[t][k]; if (v > v1) { v1 = v; i1 = k; } }
        int   i2 = -1; float v2 = -3.0e38f;
        #pragma unroll
        for (int k = 0; k < NE; k++) { float v = logits[t][k]; if (k != i1 && v > v2) { v2 = v; i2 = k; } }
        float p1 = 1.0f / (1.0f + expf(v2 - v1));
        sidx[t][0] = i1; sidx[t][1] = i2;
        sval[t][0] = p1 * SCALING; sval[t][1] = (1.0f - p1) * SCALING;
    }
    __syncthreads();

    #pragma unroll
    for (int i = 0; i < 4; i++) {
        const int idx = t + 256 * i;
        const int tk  = idx >> 5;
        const int e   = idx & 31;
        float v = 0.f;
        if (e == sidx[tk][0]) v = sval[tk][0];
        else if (e == sidx[tk][1]) v = sval[tk][1];
        wout[(tok0 + tk) * NE + e] = v;
    }
}

// ---------------------------------------------------------------------------
// Kernel 2/3: multistage cp.async FP16 mma.sync GEMM, dual K-segment.
//   C[m,n] = sum A1[m,:]W1[n,:] (+ sum A2[m,:]W2[n,:]),  fp32 accumulate.
// m16n8k16.f16: 4096 FLOP/instr — 2x the tf32 m16n8k8 rate at equal issue.
// CTA 128x128, BK=32 halves, 4 stages, 256 threads, 2x4 warp grid, 64x32
// warp tile, occupancy 2.
// Smem row stride 40 halves (80B): rows 16B-aligned for cp.async; fragment
// LDS conflict-audited; STS achieves the 4-phase minimum.
// One __syncthreads per K-tile; issue(kt+3) targets buffer (kt-1)%4 — all
// threads past barrier(kt) have finished compute(kt-1), so reuse is safe.
// EPI==1: scale by wg[row*NE + col/16], emit fp16 (feeds gemm3 K-segment 2).
// ---------------------------------------------------------------------------
#define BK     32                   // halves per K-tile
#define LDH    40                   // padded row stride (halves), 80 B
#define TSTR   (128 * LDH)          // halves per tile buffer
#define STAGES 4

template<int EPI>
__global__ __launch_bounds__(256, 2)
void mma_gemm(const __half* __restrict__ A1, const __half* __restrict__ W1, int k1, int nt1,
              const __half* __restrict__ A2, const __half* __restrict__ W2, int k2, int nt2,
              float* __restrict__ Cf, __half* __restrict__ Ch, int Nout,
              const float* __restrict__ wg)
{
    extern __shared__ __half sh[];   // [4 A-stages][4 B-stages]

    const int t    = threadIdx.x;
    const int warp = t >> 5;
    const int lane = t & 31;
    const int m0   = blockIdx.y * 128;
    const int n0   = blockIdx.x * 128;
    const int wm   = (warp & 1) * 64;
    const int wn   = (warp >> 1) * 32;
    const int g    = lane >> 2;
    const int tg   = lane & 3;
    const int nt   = nt1 + nt2;

    float acc[4][4][4];
    #pragma unroll
    for (int i = 0; i < 4; i++)
        #pragma unroll
        for (int j = 0; j < 4; j++)
            #pragma unroll
            for (int k = 0; k < 4; k++)
                acc[i][j][k] = 0.f;

    const uint32_t smU = smem_u32(sh);

    auto issue = [&](int kt, int s) {
        const __half* As; const __half* Ws; int ks_, koff;
        if (kt < nt1) { As = A1; Ws = W1; ks_ = k1; koff = kt * BK; }
        else          { As = A2; Ws = W2; ks_ = k2; koff = (kt - nt1) * BK; }
        const uint32_t aU = smU + (uint32_t)(s * TSTR) * 2u;
        const uint32_t bU = smU + (uint32_t)((STAGES + s) * TSTR) * 2u;
        #pragma unroll
        for (int i = 0; i < 2; i++) {          // A: 128 rows x 4 chunks(16B)
            const int ch = i * 256 + t;
            const int row = ch >> 2, kc = (ch & 3) * 8;      // halves
            CP_ASYNC16(aU + (uint32_t)(row * LDH + kc) * 2u,
                       As + (size_t)(m0 + row) * ks_ + koff + kc);
        }
        #pragma unroll
        for (int i = 0; i < 2; i++) {          // B: 128 rows x 4 chunks
            const int ch = i * 256 + t;
            const int row = ch >> 2, kc = (ch & 3) * 8;
            CP_ASYNC16(bU + (uint32_t)(row * LDH + kc) * 2u,
                       Ws + (size_t)(n0 + row) * ks_ + koff + kc);
        }
    };

    // prologue: stages 0..2 in flight
    issue(0, 0); CP_COMMIT();
    issue(1, 1); CP_COMMIT();
    issue(2, 2); CP_COMMIT();

    for (int kt = 0; kt < nt; kt++) {
        const int s = kt % STAGES;
        CP_WAIT(2);                 // tile kt's group complete
        __syncthreads();

        const __half* as = sh + s * TSTR;
        const __half* bs = sh + (STAGES + s) * TSTR;

        #pragma unroll
        for (int step = 0; step < 2; step++) {   // 2 x k16 per 32-half tile
            const int ks = step * 16;
            uint32_t af[4][4], bf[4][2];
            #pragma unroll
            for (int i = 0; i < 4; i++) {
                const int mb = wm + i * 16;
                af[i][0] = *(const uint32_t*)&as[(mb + g    ) * LDH + ks + 2 * tg    ];
                af[i][1] = *(const uint32_t*)&as[(mb + g + 8) * LDH + ks + 2 * tg    ];
                af[i][2] = *(const uint32_t*)&as[(mb + g    ) * LDH + ks + 2 * tg + 8];
                af[i][3] = *(const uint32_t*)&as[(mb + g + 8) * LDH + ks + 2 * tg + 8];
            }
            #pragma unroll
            for (int j = 0; j < 4; j++) {
                const int nb = wn + j * 8 + g;
                bf[j][0] = *(const uint32_t*)&bs[nb * LDH + ks + 2 * tg    ];
                bf[j][1] = *(const uint32_t*)&bs[nb * LDH + ks + 2 * tg + 8];
            }
            #pragma unroll
            for (int i = 0; i < 4; i++)
                #pragma unroll
                for (int j = 0; j < 4; j++)
                    mma_f16(acc[i][j], af[i], bf[j]);
        }

        if (kt + 3 < nt) issue(kt + 3, (kt + 3) % STAGES);
        CP_COMMIT();                // one commit per iteration keeps group count aligned
    }

    // epilogue
    #pragma unroll
    for (int i = 0; i < 4; i++) {
        const int mrow = m0 + wm + i * 16 + g;
        #pragma unroll
        for (int j = 0; j < 4; j++) {
            const int ncol = n0 + wn + j * 8 + tg * 2;
            if (EPI) {   // scale + emit fp16 (consumed by gemm3 as MMA operand)
                const float s0 = wg[(size_t)mrow       * NE + (ncol >> 4)];
                const float s1 = wg[(size_t)(mrow + 8) * NE + (ncol >> 4)];
                __half2 h0 = __floats2half2_rn(acc[i][j][0] * s0, acc[i][j][1] * s0);
                __half2 h1 = __floats2half2_rn(acc[i][j][2] * s1, acc[i][j][3] * s1);
                *(__half2*)&Ch[(size_t)mrow       * Nout + ncol] = h0;
                *(__half2*)&Ch[(size_t)(mrow + 8) * Nout + ncol] = h1;
            } else {
                float2 v0; v0.x = acc[i][j][0]; v0.y = acc[i][j][1];
                float2 v1; v1.x = acc[i][j][2]; v1.y = acc[i][j][3];
                *(float2*)&Cf[(size_t)mrow       * Nout + ncol] = v0;
                *(float2*)&Cf[(size_t)(mrow + 8) * Nout + ncol] = v1;
            }
        }
    }
}

// ---------------------------------------------------------------------------
// launch
// ---------------------------------------------------------------------------
extern "C" void kernel_launch(void* const* d_in, const int* in_sizes, int n_in,
                              void* d_out, int out_size) {
    const float* x      = (const float*)d_in[0];
    const float* base_w = (const float*)d_in[1];
    const float* gate_w = (const float*)d_in[2];
    const float* lora_A = (const float*)d_in[3];
    const float* lora_B = (const float*)d_in[4];
    float* out = (float*)d_out;

    __half *xh, *bwh, *lah, *lbh, *axw;
    float *wbuf;
    cudaGetSymbolAddress((void**)&xh,   g_xh);
    cudaGetSymbolAddress((void**)&bwh,  g_bwh);
    cudaGetSymbolAddress((void**)&lah,  g_lah);
    cudaGetSymbolAddress((void**)&lbh,  g_lbh);
    cudaGetSymbolAddress((void**)&axw,  g_axw);
    cudaGetSymbolAddress((void**)&wbuf, g_w);

    const int smem = STAGES * 2 * TSTR * 2;   // 81920 B
    cudaFuncSetAttribute(mma_gemm<0>, cudaFuncAttributeMaxDynamicSharedMemorySize, smem);
    cudaFuncSetAttribute(mma_gemm<1>, cudaFuncAttributeMaxDynamicSharedMemorySize, smem);

    // 0) convert GEMM operands to fp16 (RN)
    cvt_kernel<<<2048, 256>>>(x,      xh,  (int)((size_t)M_TOK * D_IN / 4));
    cvt_kernel<<<1024, 256>>>(base_w, bwh, (int)((size_t)D_OUT * D_IN / 4));
    cvt_kernel<<<512,  256>>>(lora_A, lah, (int)((size_t)ER * D_IN / 4));
    cvt_kernel<<<512,  256>>>(lora_B, lbh, (int)((size_t)D_OUT * ER / 4));

    // 1) gate weights (original fp32 x)
    gate_kernel<<<M_TOK / GT_TOK, 256>>>(x, gate_w, wbuf);

    // 2) axw = (x @ lora_A^T) * w * SCALING   [8192, 512] fp16
    {
        dim3 grid(ER / 128, M_TOK / 128);     // (4, 64)
        mma_gemm<1><<<grid, 256, smem>>>(xh, lah, D_IN, D_IN / BK,
                                         (const __half*)nullptr, (const __half*)nullptr, 0, 0,
                                         nullptr, axw, ER, wbuf);
    }

    // 3) out = x @ base_w^T + axw @ lora_B^T  [8192, 4096] fp32
    {
        dim3 grid(D_OUT / 128, M_TOK / 128);  // (32, 64)
        mma_gemm<0><<<grid, 256, smem>>>(xh, bwh, D_IN, D_IN / BK,
                                         axw, lbh, ER, ER / BK,
                                         out, nullptr, D_OUT, nullptr);
    }
}